// round 9
// baseline (speedup 1.0000x reference)
#include <cuda_runtime.h>
#include <cstdint>

// Problem constants
#define BB      64
#define TT      2048
#define NIN     64
#define NH      512
#define NOUT    64
#define FPIT    60
#define TOTIT   (FPIT + TT)

// Decomposition
#define CSIZE   8            // CTAs per cluster (H split: 64 rows each)
#define NCLUST  16           // clusters: 2 streams x 2 batches each
#define ROWS    64           // H rows owned per CTA
#define THREADS 512          // 16 warps; A in regs: 4 rows x 18 j = 72 f32/thread
#define NWARP   16
#define RPW     4            // rows per warp
#define JEXT    (NH + NIN)   // 576
#define KPT     18           // j's per lane: j = lane + 32k, k<18

typedef unsigned long long ull;

struct Smem {
    float hx[2][2][JEXT][2];     // [stream][buf][j][batch]
    float Wl[8][NH];             // this rank's 8 W_lin rows
    ull   full[2][2];            // [stream][buf] mbarriers (count=128)
};
#define SMEM_BYTES  ((int)sizeof(Smem))
#define HXB_BYTES   (JEXT * 2 * 4)       // 4608 per buffer
#define HX_OFF(s, b) ((uint32_t)(((s) * 2 + (b)) * HXB_BYTES))

__device__ __forceinline__ uint32_t smem_u32(const void* p) {
    uint32_t a;
    asm("{ .reg .u64 t; cvta.to.shared.u64 t, %1; cvt.u32.u64 %0, t; }"
        : "=r"(a) : "l"(p));
    return a;
}
__device__ __forceinline__ uint32_t mapa_u32(uint32_t addr, uint32_t rank) {
    uint32_t r;
    asm("mapa.shared::cluster.u32 %0, %1, %2;" : "=r"(r) : "r"(addr), "r"(rank));
    return r;
}
__device__ __forceinline__ ull pack2(float a) {
    ull r;
    asm("mov.b64 %0, {%1, %1};" : "=l"(r) : "r"(__float_as_uint(a)));
    return r;
}
__device__ __forceinline__ ull packab(float a, float b) {
    ull r;
    asm("mov.b64 %0, {%1, %2};" : "=l"(r) : "r"(__float_as_uint(a)), "r"(__float_as_uint(b)));
    return r;
}
__device__ __forceinline__ void unpack2(ull v, float& a, float& b) {
    uint32_t x, y;
    asm("mov.b64 {%0, %1}, %2;" : "=r"(x), "=r"(y) : "l"(v));
    a = __uint_as_float(x); b = __uint_as_float(y);
}
__device__ __forceinline__ void ffma2(ull& acc, ull a, ull b) {
    asm("fma.rn.f32x2 %0, %1, %2, %0;" : "+l"(acc) : "l"(a), "l"(b));
}
__device__ __forceinline__ ull addf2(ull a, ull b) {
    ull r;
    asm("add.rn.f32x2 %0, %1, %2;" : "=l"(r) : "l"(a), "l"(b));
    return r;
}
__device__ __forceinline__ float tanh_fast(float x) {
    float r;
    asm("tanh.approx.f32 %0, %1;" : "=f"(r) : "f"(x));
    return r;
}

#define MBARRIER_INIT(addr, cnt) \
    asm volatile("mbarrier.init.shared.b64 [%0], %1;" :: "r"(addr), "r"(cnt) : "memory")

#define MBAR_ARRIVE_REMOTE(addr) \
    asm volatile("mbarrier.arrive.release.cluster.shared::cluster.b64 _, [%0];" \
                 :: "r"(addr) : "memory")

#define MBAR_WAIT_CLUSTER(mbar, parity) do {                                     \
    uint32_t _m = (mbar), _p = (parity);                                         \
    asm volatile(                                                                \
        "{\n\t.reg .pred P1;\n\t"                                                \
        "WL_%=:\n\t"                                                             \
        "mbarrier.try_wait.parity.acquire.cluster.shared::cta.b64 P1, [%0], %1, 0x989680;\n\t" \
        "@P1 bra.uni WD_%=;\n\t"                                                 \
        "bra.uni WL_%=;\n\t"                                                     \
        "WD_%=:\n\t}"                                                            \
        :: "r"(_m), "r"(_p) : "memory");                                         \
} while (0)

// Head for stream s (2 batches): warp w (<8) owns output column rank*8 + w.
__device__ __forceinline__ void do_head(const Smem* S, const ull* hp, int w,
                                        int lane, int pb0, int s, int rank,
                                        float blr, int tt, float* __restrict__ out)
{
    ull acc = 0ull;
    const float* wl = &S->Wl[w][0];
    #pragma unroll
    for (int k = 0; k < 16; ++k) {
        int j = k * 32 + lane;
        ffma2(acc, pack2(wl[j]), hp[j]);
    }
    #pragma unroll
    for (int m = 16; m >= 1; m >>= 1)
        acc = addf2(acc, __shfl_xor_sync(0xffffffffu, acc, m));
    if (lane < 2) {
        float s0, s1;
        unpack2(acc, s0, s1);
        float v = lane ? s1 : s0;
        out[(pb0 + s * 2 + lane) * (TT * NOUT) + tt * NOUT + rank * 8 + w] = v + blr;
    }
}

extern __shared__ float smem_raw[];

__global__ void __cluster_dims__(CSIZE, 1, 1) __launch_bounds__(THREADS, 1)
rnn_lyapunov_kernel(const float* __restrict__ u,
                    const float* __restrict__ W_ih,
                    const float* __restrict__ W_hh,
                    const float* __restrict__ b_ih,
                    const float* __restrict__ b_hh,
                    const float* __restrict__ omega,
                    const float* __restrict__ W_lin,
                    const float* __restrict__ b_lin,
                    float* __restrict__ out)
{
    Smem* S = reinterpret_cast<Smem*>(smem_raw);
    const int tid  = threadIdx.x;
    const int w    = tid >> 5;
    const int lane = tid & 31;

    uint32_t rank;
    asm("mov.u32 %0, %%cluster_ctarank;" : "=r"(rank));
    const int cid = blockIdx.x >> 3;
    const int r0  = (int)rank * ROWS;
    const int pb0 = cid * 4;

    // ---- A into registers: 4 rows x 18 j per thread ----
    float Areg[RPW * KPT];
    {
        const int rg0 = r0 + w * RPW;
        #pragma unroll
        for (int r = 0; r < RPW; ++r) {
            const int rg = rg0 + r;
            #pragma unroll
            for (int k = 0; k < 16; ++k) {
                int j = lane + 32 * k;
                float om = omega[j];
                Areg[r * KPT + k] = W_hh[rg * NH + j] * om * om;
            }
            Areg[r * KPT + 16] = W_ih[rg * NIN + lane];
            Areg[r * KPT + 17] = W_ih[rg * NIN + 32 + lane];
        }
    }

    // ---- SMEM one-time loads ----
    for (int idx = tid; idx < 8 * NH; idx += THREADS) {
        int o = idx >> 9;
        int j = idx & (NH - 1);
        S->Wl[o][j] = W_lin[((int)rank * 8 + o) * NH + j];
    }
    // hx[s][0]: h zero, u rows = u[:,0,:]
    for (int idx = tid; idx < 2 * 2 * JEXT * 2; idx += THREADS)
        (&S->hx[0][0][0][0])[idx] = 0.0f;
    __syncthreads();
    if (tid < 128) {
        int b = tid & 1, ju = tid >> 1;
        S->hx[0][0][NH + ju][b] = u[(pb0 + 0 + b) * (TT * NIN) + ju];
        S->hx[1][0][NH + ju][b] = u[(pb0 + 2 + b) * (TT * NIN) + ju];
    }
    if (tid == 0) {
        MBARRIER_INIT(smem_u32(&S->full[0][0]), NWARP * CSIZE);
        MBARRIER_INIT(smem_u32(&S->full[0][1]), NWARP * CSIZE);
        MBARRIER_INIT(smem_u32(&S->full[1][0]), NWARP * CSIZE);
        MBARRIER_INIT(smem_u32(&S->full[1][1]), NWARP * CSIZE);
    }
    __syncthreads();
    asm volatile("barrier.cluster.arrive.aligned;" ::: "memory");
    asm volatile("barrier.cluster.wait.aligned;"   ::: "memory");

    // ---- per-thread precomputation ----
    // after the reduce, this lane holds full row i_loc and serves rank lane&7
    const int rl    = (lane >> 3) & 3;
    const int i_loc = w * RPW + rl;
    const float bias_r = b_ih[r0 + i_loc] + b_hh[r0 + i_loc];
    const float blr    = (w < 8) ? b_lin[(int)rank * 8 + w] : 0.0f;
    const uint32_t rowbase = smem_u32(&S->hx[0][0][r0 + i_loc][0]);
    const uint32_t dst = mapa_u32(rowbase, (uint32_t)(lane & 7));
    // remote arrive addresses: lanes 0-7 of EVERY warp, per stream/buffer
    uint32_t ra[2][2] = {{0, 0}, {0, 0}};
    if (lane < 8) {
        ra[0][0] = mapa_u32(smem_u32(&S->full[0][0]), (uint32_t)lane);
        ra[0][1] = mapa_u32(smem_u32(&S->full[0][1]), (uint32_t)lane);
        ra[1][0] = mapa_u32(smem_u32(&S->full[1][0]), (uint32_t)lane);
        ra[1][1] = mapa_u32(smem_u32(&S->full[1][1]), (uint32_t)lane);
    }
    uint32_t flw[2][2];
    flw[0][0] = smem_u32(&S->full[0][0]);
    flw[0][1] = smem_u32(&S->full[0][1]);
    flw[1][0] = smem_u32(&S->full[1][0]);
    flw[1][1] = smem_u32(&S->full[1][1]);

    const int ub = tid & 1;      // u prefetch: batch (tid<128, warps 0-3)
    const int ju = tid >> 1;     // u prefetch: input idx

    for (int kk = 0; kk < TOTIT; ++kk) {
        const int cur = kk & 1;
        const int nxt = cur ^ 1;
        const int t   = kk - FPIT;

        #pragma unroll
        for (int s = 0; s < 2; ++s) {
            // u prefetch for step kk+1 (issued before the wait; hidden)
            float u_next = 0.0f;
            if (tid < 128) {
                int tn = kk + 1 - FPIT;
                tn = (tn < 0) ? 0 : ((tn > TT - 1) ? (TT - 1) : tn);
                u_next = u[(pb0 + s * 2 + ub) * (TT * NIN) + tn * NIN + ju];
            }

            // wait for hx[s][cur] (skip step 0: locally initialized)
            if (kk > 0)
                MBAR_WAIT_CLUSTER(flw[s][cur], (uint32_t)(((kk - 1) >> 1) & 1));

            const ull* hp = reinterpret_cast<const ull*>(&S->hx[s][cur][0][0]);

            // ---- matvec from registers: 4 rows x 2 batches per thread ----
            ull d0 = 0ull, d1 = 0ull, d2 = 0ull, d3 = 0ull;
            #pragma unroll
            for (int k = 0; k < KPT; ++k) {
                ull hv = hp[lane + 32 * k];
                ffma2(d0, pack2(Areg[0 * KPT + k]), hv);
                ffma2(d1, pack2(Areg[1 * KPT + k]), hv);
                ffma2(d2, pack2(Areg[2 * KPT + k]), hv);
                ffma2(d3, pack2(Areg[3 * KPT + k]), hv);
            }

            // ---- distribute-reduce within the warp ----
            // L1 (xor16): keep rows {0,1} (lo half) or {2,3} (hi half)
            ull dd;
            {
                const bool hi = (lane & 16) != 0;
                ull sA = hi ? d0 : d2;
                ull sB = hi ? d1 : d3;
                ull rA = __shfl_xor_sync(0xffffffffu, sA, 16);
                ull rB = __shfl_xor_sync(0xffffffffu, sB, 16);
                ull e0 = addf2(hi ? d2 : d0, rA);
                ull e1 = addf2(hi ? d3 : d1, rB);
                // L2 (xor8): keep one row -> rl = (lane>>3)&3
                const bool b3 = (lane & 8) != 0;
                ull sC = b3 ? e0 : e1;
                ull rC = __shfl_xor_sync(0xffffffffu, sC, 8);
                dd = addf2(b3 ? e1 : e0, rC);
            }
            // L3-L5: butterfly over lane bits 2..0 (8 copies per row)
            dd = addf2(dd, __shfl_xor_sync(0xffffffffu, dd, 4));
            dd = addf2(dd, __shfl_xor_sync(0xffffffffu, dd, 2));
            dd = addf2(dd, __shfl_xor_sync(0xffffffffu, dd, 1));

            // ---- bias + tanh + DSMEM push (1 row -> rank lane&7) ----
            {
                float s0, s1;
                unpack2(dd, s0, s1);
                const float h0 = tanh_fast(s0 + bias_r);
                const float h1 = tanh_fast(s1 + bias_r);
                const ull pk = packab(h0, h1);
                asm volatile("st.shared::cluster.b64 [%0], %1;"
                             :: "r"(dst + HX_OFF(s, nxt)), "l"(pk) : "memory");
            }
            // next step's input rows (local; warps 0-3)
            if (tid < 128)
                S->hx[s][nxt][NH + ju][ub] = u_next;

            // head for step t-1 BEFORE arrive (reads hx[s][cur]; keeps the
            // buffer-reuse ordering through the barrier chain race-free)
            if (w < 8 && t >= 1)
                do_head(S, hp, w, lane, pb0, s, (int)rank, blr, t - 1, out);

            // per-warp release: my lanes' stores (+ u rows) then arrive at
            // every CTA's full[s][nxt]
            __syncwarp();
            if (lane < 8)
                MBAR_ARRIVE_REMOTE(ra[s][nxt]);
        }
    }

    // final heads: h_{TT-1} lives in hx[s][TOTIT&1]
    if (w < 8) {
        const int buf = TOTIT & 1;
        const uint32_t par = (uint32_t)(((TOTIT - 1) >> 1) & 1);
        #pragma unroll
        for (int s = 0; s < 2; ++s) {
            MBAR_WAIT_CLUSTER(flw[s][buf], par);
            const ull* hp = reinterpret_cast<const ull*>(&S->hx[s][buf][0][0]);
            do_head(S, hp, w, lane, pb0, s, (int)rank, blr, TT - 1, out);
        }
    }
}

extern "C" void kernel_launch(void* const* d_in, const int* in_sizes, int n_in,
                              void* d_out, int out_size)
{
    const float* u     = (const float*)d_in[0];
    const float* W_ih  = (const float*)d_in[1];
    const float* W_hh  = (const float*)d_in[2];
    const float* b_ih  = (const float*)d_in[3];
    const float* b_hh  = (const float*)d_in[4];
    const float* omega = (const float*)d_in[5];
    const float* W_lin = (const float*)d_in[6];
    const float* b_lin = (const float*)d_in[7];
    float* out = (float*)d_out;

    cudaFuncSetAttribute(rnn_lyapunov_kernel,
                         cudaFuncAttributeMaxDynamicSharedMemorySize,
                         SMEM_BYTES);

    rnn_lyapunov_kernel<<<NCLUST * CSIZE, THREADS, SMEM_BYTES>>>(
        u, W_ih, W_hh, b_ih, b_hh, omega, W_lin, b_lin, out);
}

// round 10
// speedup vs baseline: 1.0306x; 1.0306x over previous
#include <cuda_runtime.h>
#include <cstdint>

// Problem constants
#define BB      64
#define TT      2048
#define NIN     64
#define NH      512
#define NOUT    64
#define FPIT    60
#define TOTIT   (FPIT + TT)

// Decomposition
#define CSIZE   8            // CTAs per cluster (H split: 64 rows each)
#define NCLUST  16           // clusters: 2 streams x 2 batches each
#define ROWS    64           // H rows owned per CTA
#define THREADS 512          // 16 warps; A in regs: 4 rows x 18 j = 72 f32/thread
#define NWARP   16
#define RPW     4            // rows per warp
#define JEXT    (NH + NIN)   // 576
#define KPT     18           // j's per lane: j = lane + 32k, k<18
#define SIGW    15           // signaler warp

typedef unsigned long long ull;

struct Smem {
    float hx[2][2][JEXT][2];     // [stream][buf][j][batch]
    float Wl[8][NH];             // this rank's 8 W_lin rows
    ull   full[2][2];            // [stream][buf] cluster barriers (count=8)
    ull   loc[2][2];             // [stream][buf] local aggregation (count=16)
};
#define SMEM_BYTES  ((int)sizeof(Smem))
#define HXB_BYTES   (JEXT * 2 * 4)       // 4608 per buffer
#define HX_OFF(s, b) ((uint32_t)(((s) * 2 + (b)) * HXB_BYTES))

__device__ __forceinline__ uint32_t smem_u32(const void* p) {
    uint32_t a;
    asm("{ .reg .u64 t; cvta.to.shared.u64 t, %1; cvt.u32.u64 %0, t; }"
        : "=r"(a) : "l"(p));
    return a;
}
__device__ __forceinline__ uint32_t mapa_u32(uint32_t addr, uint32_t rank) {
    uint32_t r;
    asm("mapa.shared::cluster.u32 %0, %1, %2;" : "=r"(r) : "r"(addr), "r"(rank));
    return r;
}
__device__ __forceinline__ ull pack2(float a) {
    ull r;
    asm("mov.b64 %0, {%1, %1};" : "=l"(r) : "r"(__float_as_uint(a)));
    return r;
}
__device__ __forceinline__ ull packab(float a, float b) {
    ull r;
    asm("mov.b64 %0, {%1, %2};" : "=l"(r) : "r"(__float_as_uint(a)), "r"(__float_as_uint(b)));
    return r;
}
__device__ __forceinline__ void unpack2(ull v, float& a, float& b) {
    uint32_t x, y;
    asm("mov.b64 {%0, %1}, %2;" : "=r"(x), "=r"(y) : "l"(v));
    a = __uint_as_float(x); b = __uint_as_float(y);
}
__device__ __forceinline__ void ffma2(ull& acc, ull a, ull b) {
    asm("fma.rn.f32x2 %0, %1, %2, %0;" : "+l"(acc) : "l"(a), "l"(b));
}
__device__ __forceinline__ ull addf2(ull a, ull b) {
    ull r;
    asm("add.rn.f32x2 %0, %1, %2;" : "=l"(r) : "l"(a), "l"(b));
    return r;
}
__device__ __forceinline__ float tanh_fast(float x) {
    float r;
    asm("tanh.approx.f32 %0, %1;" : "=f"(r) : "f"(x));
    return r;
}

#define MBARRIER_INIT(addr, cnt) \
    asm volatile("mbarrier.init.shared.b64 [%0], %1;" :: "r"(addr), "r"(cnt) : "memory")

#define MBAR_ARRIVE_REMOTE(addr) \
    asm volatile("mbarrier.arrive.release.cluster.shared::cluster.b64 _, [%0];" \
                 :: "r"(addr) : "memory")

// local arrive with cluster-scope release (covers this warp's DSMEM stores)
#define MBAR_ARRIVE_LOCAL(addr) \
    asm volatile("mbarrier.arrive.release.cluster.shared::cta.b64 _, [%0];" \
                 :: "r"(addr) : "memory")

#define MBAR_WAIT_CLUSTER(mbar, parity) do {                                     \
    uint32_t _m = (mbar), _p = (parity);                                         \
    asm volatile(                                                                \
        "{\n\t.reg .pred P1;\n\t"                                                \
        "WL_%=:\n\t"                                                             \
        "mbarrier.try_wait.parity.acquire.cluster.shared::cta.b64 P1, [%0], %1, 0x989680;\n\t" \
        "@P1 bra.uni WD_%=;\n\t"                                                 \
        "bra.uni WL_%=;\n\t"                                                     \
        "WD_%=:\n\t}"                                                            \
        :: "r"(_m), "r"(_p) : "memory");                                         \
} while (0)

// Head for stream s (2 batches): warp w (<8) owns output column rank*8 + w.
__device__ __forceinline__ void do_head(const Smem* S, const ull* hp, int w,
                                        int lane, int pb0, int s, int rank,
                                        float blr, int tt, float* __restrict__ out)
{
    ull acc = 0ull;
    const float* wl = &S->Wl[w][0];
    #pragma unroll
    for (int k = 0; k < 16; ++k) {
        int j = k * 32 + lane;
        ffma2(acc, pack2(wl[j]), hp[j]);
    }
    #pragma unroll
    for (int m = 16; m >= 1; m >>= 1)
        acc = addf2(acc, __shfl_xor_sync(0xffffffffu, acc, m));
    if (lane < 2) {
        float s0, s1;
        unpack2(acc, s0, s1);
        float v = lane ? s1 : s0;
        out[(pb0 + s * 2 + lane) * (TT * NOUT) + tt * NOUT + rank * 8 + w] = v + blr;
    }
}

extern __shared__ float smem_raw[];

__global__ void __cluster_dims__(CSIZE, 1, 1) __launch_bounds__(THREADS, 1)
rnn_lyapunov_kernel(const float* __restrict__ u,
                    const float* __restrict__ W_ih,
                    const float* __restrict__ W_hh,
                    const float* __restrict__ b_ih,
                    const float* __restrict__ b_hh,
                    const float* __restrict__ omega,
                    const float* __restrict__ W_lin,
                    const float* __restrict__ b_lin,
                    float* __restrict__ out)
{
    Smem* S = reinterpret_cast<Smem*>(smem_raw);
    const int tid  = threadIdx.x;
    const int w    = tid >> 5;
    const int lane = tid & 31;

    uint32_t rank;
    asm("mov.u32 %0, %%cluster_ctarank;" : "=r"(rank));
    const int cid = blockIdx.x >> 3;
    const int r0  = (int)rank * ROWS;
    const int pb0 = cid * 4;

    // ---- A into registers: 4 rows x 18 j per thread ----
    float Areg[RPW * KPT];
    {
        const int rg0 = r0 + w * RPW;
        #pragma unroll
        for (int r = 0; r < RPW; ++r) {
            const int rg = rg0 + r;
            #pragma unroll
            for (int k = 0; k < 16; ++k) {
                int j = lane + 32 * k;
                float om = omega[j];
                Areg[r * KPT + k] = W_hh[rg * NH + j] * om * om;
            }
            Areg[r * KPT + 16] = W_ih[rg * NIN + lane];
            Areg[r * KPT + 17] = W_ih[rg * NIN + 32 + lane];
        }
    }

    // ---- SMEM one-time loads ----
    for (int idx = tid; idx < 8 * NH; idx += THREADS) {
        int o = idx >> 9;
        int j = idx & (NH - 1);
        S->Wl[o][j] = W_lin[((int)rank * 8 + o) * NH + j];
    }
    // hx[s][0]: h zero, u rows = u[:,0,:]
    for (int idx = tid; idx < 2 * 2 * JEXT * 2; idx += THREADS)
        (&S->hx[0][0][0][0])[idx] = 0.0f;
    __syncthreads();
    if (tid < 128) {
        int b = tid & 1, ju = tid >> 1;
        S->hx[0][0][NH + ju][b] = u[(pb0 + 0 + b) * (TT * NIN) + ju];
        S->hx[1][0][NH + ju][b] = u[(pb0 + 2 + b) * (TT * NIN) + ju];
    }
    if (tid == 0) {
        MBARRIER_INIT(smem_u32(&S->full[0][0]), CSIZE);
        MBARRIER_INIT(smem_u32(&S->full[0][1]), CSIZE);
        MBARRIER_INIT(smem_u32(&S->full[1][0]), CSIZE);
        MBARRIER_INIT(smem_u32(&S->full[1][1]), CSIZE);
        MBARRIER_INIT(smem_u32(&S->loc[0][0]), NWARP);
        MBARRIER_INIT(smem_u32(&S->loc[0][1]), NWARP);
        MBARRIER_INIT(smem_u32(&S->loc[1][0]), NWARP);
        MBARRIER_INIT(smem_u32(&S->loc[1][1]), NWARP);
    }
    __syncthreads();
    asm volatile("barrier.cluster.arrive.aligned;" ::: "memory");
    asm volatile("barrier.cluster.wait.aligned;"   ::: "memory");

    // ---- per-thread precomputation ----
    // after the reduce, this lane holds full row i_loc and serves rank lane&7
    const int rl    = (lane >> 3) & 3;
    const int i_loc = w * RPW + rl;
    const float bias_r = b_ih[r0 + i_loc] + b_hh[r0 + i_loc];
    const float blr    = (w < 8) ? b_lin[(int)rank * 8 + w] : 0.0f;
    const uint32_t rowbase = smem_u32(&S->hx[0][0][r0 + i_loc][0]);
    const uint32_t dst = mapa_u32(rowbase, (uint32_t)(lane & 7));
    // remote relay addresses (signaler warp, lanes 0-7)
    uint32_t ra[2][2] = {{0, 0}, {0, 0}};
    if (w == SIGW && lane < 8) {
        ra[0][0] = mapa_u32(smem_u32(&S->full[0][0]), (uint32_t)lane);
        ra[0][1] = mapa_u32(smem_u32(&S->full[0][1]), (uint32_t)lane);
        ra[1][0] = mapa_u32(smem_u32(&S->full[1][0]), (uint32_t)lane);
        ra[1][1] = mapa_u32(smem_u32(&S->full[1][1]), (uint32_t)lane);
    }
    uint32_t flw[2][2], lcw[2][2];
    #pragma unroll
    for (int s = 0; s < 2; ++s)
        #pragma unroll
        for (int b = 0; b < 2; ++b) {
            flw[s][b] = smem_u32(&S->full[s][b]);
            lcw[s][b] = smem_u32(&S->loc[s][b]);
        }

    const int ub = tid & 1;      // u prefetch: batch (tid<128, warps 0-3)
    const int ju = tid >> 1;     // u prefetch: input idx

    for (int kk = 0; kk < TOTIT; ++kk) {
        const int cur = kk & 1;
        const int nxt = cur ^ 1;
        const int t   = kk - FPIT;

        #pragma unroll
        for (int s = 0; s < 2; ++s) {
            // u prefetch for step kk+1 (issued before the wait; hidden)
            float u_next = 0.0f;
            if (tid < 128) {
                int tn = kk + 1 - FPIT;
                tn = (tn < 0) ? 0 : ((tn > TT - 1) ? (TT - 1) : tn);
                u_next = u[(pb0 + s * 2 + ub) * (TT * NIN) + tn * NIN + ju];
            }

            // wait for hx[s][cur] (skip step 0: locally initialized)
            if (kk > 0)
                MBAR_WAIT_CLUSTER(flw[s][cur], (uint32_t)(((kk - 1) >> 1) & 1));

            const ull* hp = reinterpret_cast<const ull*>(&S->hx[s][cur][0][0]);

            // ---- matvec from registers: 4 rows x 2 batches per thread ----
            ull d0 = 0ull, d1 = 0ull, d2 = 0ull, d3 = 0ull;
            #pragma unroll
            for (int k = 0; k < KPT; ++k) {
                ull hv = hp[lane + 32 * k];
                ffma2(d0, pack2(Areg[0 * KPT + k]), hv);
                ffma2(d1, pack2(Areg[1 * KPT + k]), hv);
                ffma2(d2, pack2(Areg[2 * KPT + k]), hv);
                ffma2(d3, pack2(Areg[3 * KPT + k]), hv);
            }

            // ---- distribute-reduce within the warp ----
            ull dd;
            {
                const bool hi = (lane & 16) != 0;
                ull sA = hi ? d0 : d2;
                ull sB = hi ? d1 : d3;
                ull rA = __shfl_xor_sync(0xffffffffu, sA, 16);
                ull rB = __shfl_xor_sync(0xffffffffu, sB, 16);
                ull e0 = addf2(hi ? d2 : d0, rA);
                ull e1 = addf2(hi ? d3 : d1, rB);
                const bool b3 = (lane & 8) != 0;
                ull sC = b3 ? e0 : e1;
                ull rC = __shfl_xor_sync(0xffffffffu, sC, 8);
                dd = addf2(b3 ? e1 : e0, rC);
            }
            dd = addf2(dd, __shfl_xor_sync(0xffffffffu, dd, 4));
            dd = addf2(dd, __shfl_xor_sync(0xffffffffu, dd, 2));
            dd = addf2(dd, __shfl_xor_sync(0xffffffffu, dd, 1));

            // ---- bias + tanh + DSMEM push (1 row -> rank lane&7) ----
            {
                float s0, s1;
                unpack2(dd, s0, s1);
                const float h0 = tanh_fast(s0 + bias_r);
                const float h1 = tanh_fast(s1 + bias_r);
                const ull pk = packab(h0, h1);
                asm volatile("st.shared::cluster.b64 [%0], %1;"
                             :: "r"(dst + HX_OFF(s, nxt)), "l"(pk) : "memory");
            }
            // next step's input rows (local; warps 0-3)
            if (tid < 128)
                S->hx[s][nxt][NH + ju][ub] = u_next;

            // head for step t-1 BEFORE our arrive (all reads of hx[s][cur]
            // must precede our contribution to full[s][nxt])
            if (w < 8 && t >= 1)
                do_head(S, hp, w, lane, pb0, s, (int)rank, blr, t - 1, out);

            // per-warp local arrive (elected lane, release covers warp stores)
            __syncwarp();
            if (lane == 0)
                MBAR_ARRIVE_LOCAL(lcw[s][nxt]);

            // signaler: aggregate 16 local arrives, relay 1 arrive to each CTA
            if (w == SIGW) {
                MBAR_WAIT_CLUSTER(lcw[s][nxt], (uint32_t)((kk >> 1) & 1));
                if (lane < 8)
                    MBAR_ARRIVE_REMOTE(ra[s][nxt]);
            }
        }
    }

    // final heads: h_{TT-1} lives in hx[s][TOTIT&1]
    if (w < 8) {
        const int buf = TOTIT & 1;
        const uint32_t par = (uint32_t)(((TOTIT - 1) >> 1) & 1);
        #pragma unroll
        for (int s = 0; s < 2; ++s) {
            MBAR_WAIT_CLUSTER(flw[s][buf], par);
            const ull* hp = reinterpret_cast<const ull*>(&S->hx[s][buf][0][0]);
            do_head(S, hp, w, lane, pb0, s, (int)rank, blr, TT - 1, out);
        }
    }
}

extern "C" void kernel_launch(void* const* d_in, const int* in_sizes, int n_in,
                              void* d_out, int out_size)
{
    const float* u     = (const float*)d_in[0];
    const float* W_ih  = (const float*)d_in[1];
    const float* W_hh  = (const float*)d_in[2];
    const float* b_ih  = (const float*)d_in[3];
    const float* b_hh  = (const float*)d_in[4];
    const float* omega = (const float*)d_in[5];
    const float* W_lin = (const float*)d_in[6];
    const float* b_lin = (const float*)d_in[7];
    float* out = (float*)d_out;

    cudaFuncSetAttribute(rnn_lyapunov_kernel,
                         cudaFuncAttributeMaxDynamicSharedMemorySize,
                         SMEM_BYTES);

    rnn_lyapunov_kernel<<<NCLUST * CSIZE, THREADS, SMEM_BYTES>>>(
        u, W_ih, W_hh, b_ih, b_hh, omega, W_lin, b_lin, out);
}

// round 11
// speedup vs baseline: 1.6627x; 1.6133x over previous
#include <cuda_runtime.h>
#include <cstdint>

// Problem constants
#define BB      64
#define TT      2048
#define NIN     64
#define NH      512
#define NOUT    64
#define FPIT    60
#define TOTIT   (FPIT + TT)

// Decomposition (round-7 proven): 8 CTAs/cluster, 16 clusters,
// 2 streams x 2 batches per cluster, 256 threads, A in registers.
#define CSIZE   8
#define NCLUST  16
#define ROWS    64
#define THREADS 256
#define JEXT    (NH + NIN)   // 576
#define KPT     18           // j's per lane: j = lane + 32k
#define NBUF    3            // triple buffer

typedef unsigned long long ull;

struct Smem {
    float hx[2][NBUF][JEXT][2];   // [stream][buf][j][batch]
    float Wl[8][NH];              // this rank's 8 W_lin rows
    uint32_t flags[2][NBUF][8];   // [stream][buf][src_rank] = step counter
};
#define SMEM_BYTES  ((int)sizeof(Smem))
#define HXB_BYTES   (JEXT * 2 * 4)                        // 4608 per buffer
#define HX_OFF(s, b) ((uint32_t)(((s) * NBUF + (b)) * HXB_BYTES))
#define FL_OFF(s, b) ((uint32_t)(((s) * NBUF + (b)) * 32))

__device__ __forceinline__ uint32_t smem_u32(const void* p) {
    uint32_t a;
    asm("{ .reg .u64 t; cvta.to.shared.u64 t, %1; cvt.u32.u64 %0, t; }"
        : "=r"(a) : "l"(p));
    return a;
}
__device__ __forceinline__ uint32_t mapa_u32(uint32_t addr, uint32_t rank) {
    uint32_t r;
    asm("mapa.shared::cluster.u32 %0, %1, %2;" : "=r"(r) : "r"(addr), "r"(rank));
    return r;
}
__device__ __forceinline__ ull pack2(float a) {
    ull r;
    asm("mov.b64 %0, {%1, %1};" : "=l"(r) : "r"(__float_as_uint(a)));
    return r;
}
__device__ __forceinline__ ull packab(float a, float b) {
    ull r;
    asm("mov.b64 %0, {%1, %2};" : "=l"(r) : "r"(__float_as_uint(a)), "r"(__float_as_uint(b)));
    return r;
}
__device__ __forceinline__ void unpack2(ull v, float& a, float& b) {
    uint32_t x, y;
    asm("mov.b64 {%0, %1}, %2;" : "=r"(x), "=r"(y) : "l"(v));
    a = __uint_as_float(x); b = __uint_as_float(y);
}
__device__ __forceinline__ void ffma2(ull& acc, ull a, ull b) {
    asm("fma.rn.f32x2 %0, %1, %2, %0;" : "+l"(acc) : "l"(a), "l"(b));
}
__device__ __forceinline__ ull addf2(ull a, ull b) {
    ull r;
    asm("add.rn.f32x2 %0, %1, %2;" : "=l"(r) : "l"(a), "l"(b));
    return r;
}
__device__ __forceinline__ float tanh_fast(float x) {
    float r;
    asm("tanh.approx.f32 %0, %1;" : "=f"(r) : "f"(x));
    return r;
}

// flag publish: release store orders all our CTA's prior (bar.sync-ordered)
// DSMEM data stores before the flag becomes visible at cluster scope
#define FLAG_PUB(addr, val) \
    asm volatile("st.release.cluster.shared::cluster.u32 [%0], %1;" \
                 :: "r"(addr), "r"(val) : "memory")

// poll one flag word (this CTA's SMEM, written remotely) until >= need.
// All 32 lanes participate; lane polls flags[lane&7].
__device__ __forceinline__ void flag_wait(uint32_t addr, uint32_t need) {
    uint32_t v;
    do {
        asm volatile("ld.acquire.cluster.shared::cta.u32 %0, [%1];"
                     : "=r"(v) : "r"(addr) : "memory");
    } while (__any_sync(0xffffffffu, v < need));
}

// Head for stream s (2 batches): warp w owns output column rank*8 + w.
__device__ __forceinline__ void do_head(const Smem* S, const ull* hp, int w,
                                        int lane, int pb0, int s, int rank,
                                        float blr, int tt, float* __restrict__ out)
{
    ull acc = 0ull;
    const float* wl = &S->Wl[w][0];
    #pragma unroll
    for (int k = 0; k < 16; ++k) {
        int j = k * 32 + lane;
        ffma2(acc, pack2(wl[j]), hp[j]);
    }
    #pragma unroll
    for (int m = 16; m >= 1; m >>= 1)
        acc = addf2(acc, __shfl_xor_sync(0xffffffffu, acc, m));
    if (lane < 2) {
        float s0, s1;
        unpack2(acc, s0, s1);
        float v = lane ? s1 : s0;
        out[(pb0 + s * 2 + lane) * (TT * NOUT) + tt * NOUT + rank * 8 + w] = v + blr;
    }
}

extern __shared__ float smem_raw[];

__global__ void __cluster_dims__(CSIZE, 1, 1) __launch_bounds__(THREADS, 1)
rnn_lyapunov_kernel(const float* __restrict__ u,
                    const float* __restrict__ W_ih,
                    const float* __restrict__ W_hh,
                    const float* __restrict__ b_ih,
                    const float* __restrict__ b_hh,
                    const float* __restrict__ omega,
                    const float* __restrict__ W_lin,
                    const float* __restrict__ b_lin,
                    float* __restrict__ out)
{
    Smem* S = reinterpret_cast<Smem*>(smem_raw);
    const int tid  = threadIdx.x;
    const int w    = tid >> 5;
    const int lane = tid & 31;

    uint32_t rank;
    asm("mov.u32 %0, %%cluster_ctarank;" : "=r"(rank));
    const int cid = blockIdx.x >> 3;
    const int r0  = (int)rank * ROWS;
    const int pb0 = cid * 4;

    // ---- A into registers: 8 rows x 18 j per thread ----
    float Areg[8 * KPT];
    {
        const int rg0 = r0 + w * 8;
        #pragma unroll
        for (int r = 0; r < 8; ++r) {
            const int rg = rg0 + r;
            #pragma unroll
            for (int k = 0; k < 16; ++k) {
                int j = lane + 32 * k;
                float om = omega[j];
                Areg[r * KPT + k] = W_hh[rg * NH + j] * om * om;
            }
            Areg[r * KPT + 16] = W_ih[rg * NIN + lane];
            Areg[r * KPT + 17] = W_ih[rg * NIN + 32 + lane];
        }
    }

    // ---- SMEM one-time loads ----
    for (int idx = tid; idx < 8 * NH; idx += THREADS) {
        int o = idx >> 9;
        int j = idx & (NH - 1);
        S->Wl[o][j] = W_lin[((int)rank * 8 + o) * NH + j];
    }
    // hx[s][0]: h zero, u rows = u[:,0,:]; flags zero
    for (int idx = tid; idx < 2 * NBUF * JEXT * 2; idx += THREADS)
        (&S->hx[0][0][0][0])[idx] = 0.0f;
    if (tid < 2 * NBUF * 8)
        (&S->flags[0][0][0])[tid] = 0u;
    __syncthreads();
    if (tid < 128) {
        int b = tid & 1, ju = tid >> 1;
        S->hx[0][0][NH + ju][b] = u[(pb0 + 0 + b) * (TT * NIN) + ju];
        S->hx[1][0][NH + ju][b] = u[(pb0 + 2 + b) * (TT * NIN) + ju];
    }
    __syncthreads();
    // flags + initial hx visible cluster-wide before any remote traffic
    asm volatile("barrier.cluster.arrive.aligned;" ::: "memory");
    asm volatile("barrier.cluster.wait.aligned;"   ::: "memory");

    // ---- per-thread precomputation ----
    // after the reduce, lane holds row rl = (lane>>2)&7; q = lane&3 serves
    // ranks 2q and 2q+1
    const int rl    = (lane >> 2) & 7;
    const int q     = lane & 3;
    const int i_loc = w * 8 + rl;
    const float bias_r = b_ih[r0 + i_loc] + b_hh[r0 + i_loc];
    const float blr    = b_lin[(int)rank * 8 + w];
    const uint32_t rowbase = smem_u32(&S->hx[0][0][r0 + i_loc][0]);
    const uint32_t dst0 = mapa_u32(rowbase, (uint32_t)(2 * q));
    const uint32_t dst1 = mapa_u32(rowbase, (uint32_t)(2 * q + 1));
    // flag publish base (warp 0, lanes 0-7: one destination CTA each)
    uint32_t fdst = 0;
    if (w == 0 && lane < 8)
        fdst = mapa_u32(smem_u32(&S->flags[0][0][rank]), (uint32_t)lane);
    // local poll base: lane polls flags[...][lane&7]
    const uint32_t flbase = smem_u32(&S->flags[0][0][0]) + (uint32_t)((lane & 7) * 4);

    const int ub = tid & 1;      // u prefetch: batch (tid<128)
    const int ju = tid >> 1;     // u prefetch: input idx

    int bc = 0;                  // current buffer = kk % 3
    for (int kk = 0; kk < TOTIT; ++kk) {
        const int bn = (bc == NBUF - 1) ? 0 : bc + 1;
        const int t  = kk - FPIT;

        #pragma unroll
        for (int s = 0; s < 2; ++s) {
            // u prefetch for step kk+1 (issued before the wait; hidden)
            float u_next = 0.0f;
            if (tid < 128) {
                int tn = kk + 1 - FPIT;
                tn = (tn < 0) ? 0 : ((tn > TT - 1) ? (TT - 1) : tn);
                u_next = u[(pb0 + s * 2 + ub) * (TT * NIN) + tn * NIN + ju];
            }

            // wait for hx[s][bc] (skip step 0: locally initialized)
            if (kk > 0)
                flag_wait(flbase + FL_OFF(s, bc), (uint32_t)kk);

            const ull* hp = reinterpret_cast<const ull*>(&S->hx[s][bc][0][0]);

            // ---- matvec from registers: 8 rows x 2 batches per thread ----
            ull d[8] = {0ull, 0ull, 0ull, 0ull, 0ull, 0ull, 0ull, 0ull};
            #pragma unroll
            for (int k = 0; k < KPT; ++k) {
                ull hv = hp[lane + 32 * k];
                #pragma unroll
                for (int r = 0; r < 8; ++r)
                    ffma2(d[r], pack2(Areg[r * KPT + k]), hv);
            }

            // ---- distribute-reduce within the warp ----
            {
                const bool sel = (lane & 16) != 0;
                #pragma unroll
                for (int i = 0; i < 4; ++i) {
                    ull snd = sel ? d[i] : d[i + 4];
                    ull rcv = __shfl_xor_sync(0xffffffffu, snd, 16);
                    d[i] = addf2(sel ? d[i + 4] : d[i], rcv);
                }
            }
            {
                const bool sel = (lane & 8) != 0;
                #pragma unroll
                for (int i = 0; i < 2; ++i) {
                    ull snd = sel ? d[i] : d[i + 2];
                    ull rcv = __shfl_xor_sync(0xffffffffu, snd, 8);
                    d[i] = addf2(sel ? d[i + 2] : d[i], rcv);
                }
            }
            ull dd;
            {
                const bool sel = (lane & 4) != 0;
                ull snd = sel ? d[0] : d[1];
                ull rcv = __shfl_xor_sync(0xffffffffu, snd, 4);
                dd = addf2(sel ? d[1] : d[0], rcv);
            }
            dd = addf2(dd, __shfl_xor_sync(0xffffffffu, dd, 2));
            dd = addf2(dd, __shfl_xor_sync(0xffffffffu, dd, 1));

            // ---- bias + tanh + DSMEM push (1 row -> 2 ranks) ----
            {
                float s0, s1;
                unpack2(dd, s0, s1);
                const float h0 = tanh_fast(s0 + bias_r);
                const float h1 = tanh_fast(s1 + bias_r);
                const ull pk = packab(h0, h1);
                const uint32_t off = HX_OFF(s, bn);
                asm volatile("st.shared::cluster.b64 [%0], %1;"
                             :: "r"(dst0 + off), "l"(pk) : "memory");
                asm volatile("st.shared::cluster.b64 [%0], %1;"
                             :: "r"(dst1 + off), "l"(pk) : "memory");
            }
            // next step's input rows (local)
            if (tid < 128)
                S->hx[s][bn][NH + ju][ub] = u_next;

            // order all warps' stores, then publish flags (8 parallel release
            // stores to distinct addresses -- no atomic serialization)
            __syncthreads();
            if (w == 0 && lane < 8)
                FLAG_PUB(fdst + FL_OFF(s, bn), (uint32_t)(kk + 1));

            // head for step t-1 overlapped with the exchange window.
            // Safe with triple buffering: hx[s][bc] is only rewritten by
            // producers that acquired flag kk+2, which we release only after
            // these reads (program order, next iteration).
            if (t >= 1)
                do_head(S, hp, w, lane, pb0, s, (int)rank, blr, t - 1, out);
        }
        bc = bn;
    }

    // final heads: h_{TT-1} lives in hx[s][TOTIT%3]
    {
        const int bf = TOTIT % NBUF;
        #pragma unroll
        for (int s = 0; s < 2; ++s) {
            flag_wait(flbase + FL_OFF(s, bf), (uint32_t)TOTIT);
            const ull* hp = reinterpret_cast<const ull*>(&S->hx[s][bf][0][0]);
            do_head(S, hp, w, lane, pb0, s, (int)rank, blr, TT - 1, out);
        }
    }
}

extern "C" void kernel_launch(void* const* d_in, const int* in_sizes, int n_in,
                              void* d_out, int out_size)
{
    const float* u     = (const float*)d_in[0];
    const float* W_ih  = (const float*)d_in[1];
    const float* W_hh  = (const float*)d_in[2];
    const float* b_ih  = (const float*)d_in[3];
    const float* b_hh  = (const float*)d_in[4];
    const float* omega = (const float*)d_in[5];
    const float* W_lin = (const float*)d_in[6];
    const float* b_lin = (const float*)d_in[7];
    float* out = (float*)d_out;

    cudaFuncSetAttribute(rnn_lyapunov_kernel,
                         cudaFuncAttributeMaxDynamicSharedMemorySize,
                         SMEM_BYTES);

    rnn_lyapunov_kernel<<<NCLUST * CSIZE, THREADS, SMEM_BYTES>>>(
        u, W_ih, W_hh, b_ih, b_hh, omega, W_lin, b_lin, out);
}